// round 8
// baseline (speedup 1.0000x reference)
#include <cuda_runtime.h>
#include <cuda_fp16.h>
#include <cstdint>

// ---------------------------------------------------------------------------
// SparseColumnAttention via mma.sync pure-fp16 GEMMs (sm_100 baseline).
//   x:(2,128,45,512) f32 -> R=11520 rows, C=512, N=8 heads, D=64, K=17.
// R8: QKV GEMM uses 128x256 CTA tile / 64x64 warp tile / 1 CTA/SM (255-reg
//     budget, real register double-buffering). Out-proj keeps 128x128 config.
// Error model (validated R4-R7): ~3.0e-4/GEMM, quadrature => ~4.2e-4 total.
// ---------------------------------------------------------------------------

#define ROWS 11520

__device__ float    g_qkv[ROWS * 1536];
__device__ uint32_t g_ax  [ROWS * 256];   // [90 mtile][16 kc][2048 u32]
__device__ uint32_t g_aatt[ROWS * 256];   // same layout (written by attn)
__device__ uint32_t g_bw1 [1536 * 256];   // [12 ntile][16 kc][2048 u32]
__device__ uint32_t g_bw2 [512 * 256];    // [4 ntile][...]
__device__ float    g_bias[1536];

// ------------------------------ helpers -----------------------------------
__device__ __forceinline__ uint32_t s2u32(const void* p) {
    uint32_t a;
    asm("{ .reg .u64 t; cvta.to.shared.u64 t, %1; cvt.u32.u64 %0, t; }"
        : "=r"(a) : "l"(p));
    return a;
}
__device__ __forceinline__ void cp16(uint32_t s, const void* g) {
    asm volatile("cp.async.cg.shared.global [%0], [%1], 16;" :: "r"(s), "l"(g));
}
#define CP_COMMIT() asm volatile("cp.async.commit_group;" ::: "memory")
#define CP_WAIT(n)  asm volatile("cp.async.wait_group %0;" :: "n"(n) : "memory")

__device__ __forceinline__ void lds128(uint32_t* r, uint32_t a) {
    asm volatile("ld.shared.v4.b32 {%0,%1,%2,%3}, [%4];"
                 : "=r"(r[0]), "=r"(r[1]), "=r"(r[2]), "=r"(r[3]) : "r"(a));
}
__device__ __forceinline__ void lds64(uint32_t* r, uint32_t a) {
    asm volatile("ld.shared.v2.b32 {%0,%1}, [%2];"
                 : "=r"(r[0]), "=r"(r[1]) : "r"(a));
}
__device__ __forceinline__ void mma_fp16(float* c, const uint32_t* a, const uint32_t* b) {
    asm volatile(
        "mma.sync.aligned.m16n8k16.row.col.f32.f16.f16.f32 "
        "{%0,%1,%2,%3}, {%4,%5,%6,%7}, {%8,%9}, {%0,%1,%2,%3};"
        : "+f"(c[0]), "+f"(c[1]), "+f"(c[2]), "+f"(c[3])
        : "r"(a[0]), "r"(a[1]), "r"(a[2]), "r"(a[3]), "r"(b[0]), "r"(b[1]));
}

// ------------------------------ pack A (x) ---------------------------------
__global__ __launch_bounds__(256)
void pack_a_kern(const float* __restrict__ src)
{
    const int mtile = blockIdx.x, kc = blockIdx.y, t = threadIdx.x;
    uint32_t* chunk = g_ax + ((size_t)mtile * 16 + kc) * 2048;
    const float* sbase = src + (size_t)mtile * 128 * 512 + kc * 32;
#pragma unroll
    for (int s = 0; s < 8; s++) {
        int p = t + s * 256;
        int blk = p >> 7, q = p & 127;
        int lane = q >> 2, reg = q & 3;
        int mb = blk >> 1, kb = blk & 1;
        int row = mb * 16 + (lane >> 2) + 8 * (reg & 1);
        int col = kb * 16 + (lane & 3) * 2 + 8 * (reg >> 1);
        float2 v = *(const float2*)(sbase + (size_t)row * 512 + col);
        __half2 h = __floats2half2_rn(v.x, v.y);
        chunk[p] = *(uint32_t*)&h;
    }
}

// ------------------------------ pack B (+bias) -----------------------------
__global__ __launch_bounds__(256)
void pack_w_kern(const float* __restrict__ W0, const float* __restrict__ W1,
                 const float* __restrict__ W2, int which,
                 const float* __restrict__ bq, const float* __restrict__ bk,
                 const float* __restrict__ bv)
{
    if (which == 0 && blockIdx.y == 0 && blockIdx.x < 6) {
        int i = blockIdx.x * 256 + threadIdx.x;
        g_bias[i] = (i < 512) ? bq[i] : (i < 1024 ? bk[i - 512] : bv[i - 1024]);
    }
    uint32_t* dst = which ? g_bw2 : g_bw1;
    const int ntile = blockIdx.x, kc = blockIdx.y, t = threadIdx.x;
    uint32_t* chunk = dst + ((size_t)ntile * 16 + kc) * 2048;
#pragma unroll
    for (int s = 0; s < 8; s++) {
        int p = t + s * 256;
        int blk = p >> 6, q = p & 63;
        int lane = q >> 1, reg = q & 1;
        int nb = blk >> 1, kb = blk & 1;
        int n = ntile * 128 + nb * 8 + (lane >> 2);
        int col = kc * 32 + kb * 16 + (lane & 3) * 2 + 8 * reg;
        const float* W = (n < 512) ? W0 : (n < 1024 ? W1 : W2);
        float2 v = *(const float2*)(W + (size_t)(n & 511) * 512 + col);
        __half2 h = __floats2half2_rn(v.x, v.y);
        chunk[p] = *(uint32_t*)&h;
    }
}

// ------------------- GEMM wide (QKV): 128x256, 64x64 warps -----------------
// stage 48KB = [A 16K | B_even 16K | B_odd 16K], 3 stages, Kc=64, 8 iters.
#define GWSMEM (3 * 49152)

__global__ __launch_bounds__(256, 1)
void gemm_w(void)
{
    extern __shared__ __align__(16) char smem[];
    const uint32_t sb = s2u32(smem);
    const int t = threadIdx.x;
    const int wid = t >> 5, lane = t & 31;
    const int wm = wid & 1, wn = wid >> 1;      // 2 x 4 warps of 64x64

    const uint4* Ag  = (const uint4*)g_ax + (size_t)blockIdx.x * 8192;
    const uint4* Bg0 = (const uint4*)g_bw1 + (size_t)(blockIdx.y * 2) * 8192;
    const uint4* Bg1 = Bg0 + 8192;

#define LOADW(c, stage) do {                                            \
        uint32_t s_ = sb + (stage) * 49152;                             \
        const uint4* ga_ = Ag + (c) * 1024 + t;                         \
        const uint4* g0_ = Bg0 + (c) * 1024 + t;                        \
        const uint4* g1_ = Bg1 + (c) * 1024 + t;                        \
        _Pragma("unroll")                                               \
        for (int i_ = 0; i_ < 4; i_++)                                  \
            cp16(s_ + (t + i_ * 256) * 16, ga_ + i_ * 256);             \
        _Pragma("unroll")                                               \
        for (int i_ = 0; i_ < 4; i_++)                                  \
            cp16(s_ + 16384 + (t + i_ * 256) * 16, g0_ + i_ * 256);     \
        _Pragma("unroll")                                               \
        for (int i_ = 0; i_ < 4; i_++)                                  \
            cp16(s_ + 32768 + (t + i_ * 256) * 16, g1_ + i_ * 256);     \
        CP_COMMIT();                                                    \
    } while (0)

    float acc[4][8][4];
#pragma unroll
    for (int i = 0; i < 4; i++)
#pragma unroll
        for (int j = 0; j < 8; j++)
#pragma unroll
            for (int r = 0; r < 4; r++) acc[i][j][r] = 0.f;

    LOADW(0, 0);
    LOADW(1, 1);

    uint32_t ah[2][4][4], bh[2][8][2];

    for (int c = 0; c < 8; c++) {
        if (c < 6) CP_WAIT(1);
        else       CP_WAIT(0);
        __syncthreads();

        if (c + 2 < 8) LOADW(c + 2, (c + 2) % 3);

        const uint32_t sa = sb + (c % 3) * 49152;
        const uint32_t sB = sa + 16384 + (wn >> 1) * 16384;   // even/odd ntile
        const int nbb = (wn & 1) * 8;                          // nb base in ntile

#define AADDRW(kb, i) (sa + (uint32_t)(((kb) >> 1) * 8192 + \
                        (((wm * 4 + (i)) * 2 + ((kb) & 1)) * 512 + lane * 16)))
#define BADDRW(kb, j) (sB + (uint32_t)(((kb) >> 1) * 8192 + \
                        (((nbb + (j)) * 2 + ((kb) & 1)) * 256 + lane * 8)))

#pragma unroll
        for (int i = 0; i < 4; i++) lds128(ah[0][i], AADDRW(0, i));
#pragma unroll
        for (int j = 0; j < 8; j++) lds64(bh[0][j], BADDRW(0, j));

#pragma unroll
        for (int kb = 0; kb < 4; kb++) {
            const int cur = kb & 1, nxt = cur ^ 1;
            if (kb < 3) {
#pragma unroll
                for (int i = 0; i < 4; i++) lds128(ah[nxt][i], AADDRW(kb + 1, i));
#pragma unroll
                for (int j = 0; j < 8; j++) lds64(bh[nxt][j], BADDRW(kb + 1, j));
            }
#pragma unroll
            for (int i = 0; i < 4; i++)
#pragma unroll
                for (int j = 0; j < 8; j++)
                    mma_fp16(acc[i][j], ah[cur][i], bh[cur][j]);
        }
#undef AADDRW
#undef BADDRW
    }

    const int row0 = blockIdx.x * 128 + wm * 64 + (lane >> 2);
    const int colb = blockIdx.y * 256 + wn * 64 + (lane & 3) * 2;
#pragma unroll
    for (int i = 0; i < 4; i++)
#pragma unroll
        for (int j = 0; j < 8; j++) {
            const int r = row0 + i * 16;
            const int c = colb + j * 8;
            const float b0 = __ldg(g_bias + c), b1 = __ldg(g_bias + c + 1);
            *(float2*)(g_qkv + (size_t)r * 1536 + c) =
                make_float2(acc[i][j][0] + b0, acc[i][j][1] + b1);
            *(float2*)(g_qkv + (size_t)(r + 8) * 1536 + c) =
                make_float2(acc[i][j][2] + b0, acc[i][j][3] + b1);
        }
#undef LOADW
}

// ------------------- GEMM out-proj: 128x128 (R7 config) --------------------
#define GSMEM (3 * 32768)

__global__ __launch_bounds__(256, 2)
void gemm1(const float* __restrict__ bias, float* __restrict__ C)
{
    extern __shared__ __align__(16) char smem[];
    const uint32_t sb = s2u32(smem);
    const int t = threadIdx.x;
    const int wid = t >> 5, lane = t & 31;
    const int wm = wid & 1, wn = wid >> 1;

    const uint4* Ag = (const uint4*)g_aatt + (size_t)blockIdx.x * 8192;
    const uint4* Bg = (const uint4*)g_bw2 + (size_t)blockIdx.y * 8192;

#define LOADS(c, stage) do {                                            \
        uint32_t s_ = sb + (stage) * 32768;                             \
        const uint4* ga_ = Ag + (c) * 1024 + t;                         \
        const uint4* gb_ = Bg + (c) * 1024 + t;                         \
        _Pragma("unroll")                                               \
        for (int i_ = 0; i_ < 4; i_++)                                  \
            cp16(s_ + (t + i_ * 256) * 16, ga_ + i_ * 256);             \
        _Pragma("unroll")                                               \
        for (int i_ = 0; i_ < 4; i_++)                                  \
            cp16(s_ + 16384 + (t + i_ * 256) * 16, gb_ + i_ * 256);     \
        CP_COMMIT();                                                    \
    } while (0)

    float acc[4][4][4];
#pragma unroll
    for (int i = 0; i < 4; i++)
#pragma unroll
        for (int j = 0; j < 4; j++)
#pragma unroll
            for (int r = 0; r < 4; r++) acc[i][j][r] = 0.f;

    LOADS(0, 0);
    LOADS(1, 1);

    uint32_t ah[2][4][4], bh[2][4][2];

    for (int c = 0; c < 8; c++) {
        if (c < 6) CP_WAIT(1);
        else       CP_WAIT(0);
        __syncthreads();

        if (c + 2 < 8) LOADS(c + 2, (c + 2) % 3);

        const uint32_t sa = sb + (c % 3) * 32768;
        const uint32_t sbm = sa + 16384;

#define AADDR(kb, i) (sa + (uint32_t)(((kb) >> 1) * 8192 + \
                       (((wm * 4 + (i)) * 2 + ((kb) & 1)) * 512 + lane * 16)))
#define BADDR(kb, j) (sbm + (uint32_t)(((kb) >> 1) * 8192 + \
                       (((wn * 4 + (j)) * 2 + ((kb) & 1)) * 256 + lane * 8)))

#pragma unroll
        for (int i = 0; i < 4; i++) lds128(ah[0][i], AADDR(0, i));
#pragma unroll
        for (int j = 0; j < 4; j++) lds64(bh[0][j], BADDR(0, j));

#pragma unroll
        for (int kb = 0; kb < 4; kb++) {
            const int cur = kb & 1, nxt = cur ^ 1;
            if (kb < 3) {
#pragma unroll
                for (int i = 0; i < 4; i++) lds128(ah[nxt][i], AADDR(kb + 1, i));
#pragma unroll
                for (int j = 0; j < 4; j++) lds64(bh[nxt][j], BADDR(kb + 1, j));
            }
#pragma unroll
            for (int i = 0; i < 4; i++)
#pragma unroll
                for (int j = 0; j < 4; j++)
                    mma_fp16(acc[i][j], ah[cur][i], bh[cur][j]);
        }
#undef AADDR
#undef BADDR
    }

    const int row0 = blockIdx.x * 128 + wm * 64 + (lane >> 2);
    const int colb = blockIdx.y * 128 + wn * 32 + (lane & 3) * 2;
#pragma unroll
    for (int i = 0; i < 4; i++)
#pragma unroll
        for (int j = 0; j < 4; j++) {
            const int r = row0 + i * 16;
            const int c = colb + j * 8;
            const float b0 = __ldg(bias + c), b1 = __ldg(bias + c + 1);
            *(float2*)(C + (size_t)r * 512 + c) =
                make_float2(acc[i][j][0] + b0, acc[i][j][1] + b1);
            *(float2*)(C + (size_t)(r + 8) * 512 + c) =
                make_float2(acc[i][j][2] + b0, acc[i][j][3] + b1);
        }
#undef LOADS
}

// ----------------------------- attention -----------------------------------
__global__ __launch_bounds__(256)
void attn_kernel(const int* __restrict__ pair_idxs)
{
    __shared__ float ks[45 * 64];
    __shared__ float vs[45 * 64];
    __shared__ int sp[45 * 17];

    const int bm = blockIdx.x;   // 0..255
    const int n = blockIdx.y;    // 0..7
    const int base = bm * 45;
    const int tid = threadIdx.x;

    for (int i = tid; i < 45 * 17; i += 256) sp[i] = pair_idxs[i];
    for (int i = tid; i < 45 * 16; i += 256) {
        const int r = i >> 4, c4 = (i & 15) * 4;
        const float* src = g_qkv + (size_t)(base + r) * 1536 + n * 64 + c4;
        *(float4*)&ks[r * 64 + c4] = *(const float4*)(src + 512);
        *(float4*)&vs[r * 64 + c4] = *(const float4*)(src + 1024);
    }
    __syncthreads();

    const int warp = tid >> 5, lane = tid & 31;
    for (int tt = warp; tt < 45; tt += 8) {
        const float* qrow = g_qkv + (size_t)(base + tt) * 1536 + n * 64;
        const float q0 = qrow[lane];
        const float q1 = qrow[lane + 32];

        float sc[17];
        int tj[17];
#pragma unroll
        for (int j = 0; j < 17; j++) {
            tj[j] = sp[tt * 17 + j];
            const float* krow = ks + tj[j] * 64;
            float p = q0 * krow[lane] + q1 * krow[lane + 32];
            p += __shfl_xor_sync(0xffffffffu, p, 16);
            p += __shfl_xor_sync(0xffffffffu, p, 8);
            p += __shfl_xor_sync(0xffffffffu, p, 4);
            p += __shfl_xor_sync(0xffffffffu, p, 2);
            p += __shfl_xor_sync(0xffffffffu, p, 1);
            sc[j] = p * 0.125f;
        }
        float mx = sc[0];
#pragma unroll
        for (int j = 1; j < 17; j++) mx = fmaxf(mx, sc[j]);
        float ssum = 0.f;
#pragma unroll
        for (int j = 0; j < 17; j++) { sc[j] = __expf(sc[j] - mx); ssum += sc[j]; }
        const float inv = 1.f / ssum;

        float o0 = 0.f, o1 = 0.f;
#pragma unroll
        for (int j = 0; j < 17; j++) {
            const float* vrow = vs + tj[j] * 64;
            const float w = sc[j] * inv;
            o0 += w * vrow[lane];
            o1 += w * vrow[lane + 32];
        }

        // fused pack: pair adjacent columns via shfl, write fp16 fragments.
        const float p0 = __shfl_xor_sync(0xffffffffu, o0, 1);
        const float p1 = __shfl_xor_sync(0xffffffffu, o1, 1);
        const int grow = base + tt;
        const int mtile = grow >> 7;
        const int rr = grow & 127;
        const int rbit = (rr >> 3) & 1;
        const int mb = rr >> 4;
        const int jp = lane >> 1;                 // pair index 0..15
        const int lane_t = (rr & 7) * 4 + (jp & 3);
        const int reg = rbit + 2 * ((jp >> 2) & 1);
        const int kb = jp >> 3;
        const int idx = (mb * 2 + kb) * 128 + lane_t * 4 + reg;

        uint32_t u;
        int kc;
        if ((lane & 1) == 0) {
            __half2 h = __floats2half2_rn(o0, p0);
            u = *(uint32_t*)&h;
            kc = n * 2;
        } else {
            __half2 h = __floats2half2_rn(p1, o1);
            u = *(uint32_t*)&h;
            kc = n * 2 + 1;
        }
        g_aatt[((size_t)mtile * 16 + kc) * 2048 + idx] = u;
    }
}

// ------------------------------- launch ------------------------------------
extern "C" void kernel_launch(void* const* d_in, const int* in_sizes, int n_in,
                              void* d_out, int out_size)
{
    const float* x  = (const float*)d_in[0];
    const float* Wq = (const float*)d_in[1];
    const float* bq = (const float*)d_in[2];
    const float* Wk = (const float*)d_in[3];
    const float* bk = (const float*)d_in[4];
    const float* Wv = (const float*)d_in[5];
    const float* bv = (const float*)d_in[6];
    const float* Wp = (const float*)d_in[7];
    const float* bp = (const float*)d_in[8];
    const int* pair = (const int*)d_in[9];
    float* out = (float*)d_out;
    (void)in_sizes; (void)n_in; (void)out_size;

    cudaFuncSetAttribute(gemm_w, cudaFuncAttributeMaxDynamicSharedMemorySize, GWSMEM);
    cudaFuncSetAttribute(gemm1, cudaFuncAttributeMaxDynamicSharedMemorySize, GSMEM);

    pack_a_kern<<<dim3(90, 16), 256>>>(x);
    pack_w_kern<<<dim3(12, 16), 256>>>(Wq, Wk, Wv, 0, bq, bk, bv);
    pack_w_kern<<<dim3(4, 16), 256>>>(Wp, Wp, Wp, 1, bq, bk, bv);
    gemm_w<<<dim3(90, 6), 256, GWSMEM>>>();
    attn_kernel<<<dim3(256, 8), 256>>>(pair);
    gemm1<<<dim3(90, 4), 256, GSMEM>>>(bp, out);
}

// round 9
// speedup vs baseline: 1.0034x; 1.0034x over previous
#include <cuda_runtime.h>
#include <cuda_fp16.h>
#include <cstdint>

// ---------------------------------------------------------------------------
// SparseColumnAttention via mma.sync pure-fp16 GEMMs (sm_100 baseline).
//   x:(2,128,45,512) f32 -> R=11520 rows, C=512, N=8 heads, D=64, K=17.
// R9: single pack kernel; QKV GEMM = R7 128x128 config (measured floor);
//     out-proj GEMM 64x128 tiles (tail quantization fix); attn with 8-lane
//     d-split (3 shfl/score, shfl-free fragment output).
// Error model (validated R4-R8): ~3.0e-4/GEMM, quadrature => ~4.2e-4 total.
// ---------------------------------------------------------------------------

#define ROWS 11520

__device__ float    g_qkv[ROWS * 1536];
__device__ uint32_t g_ax  [ROWS * 256];   // [90 mtile][16 kc][2048 u32]
__device__ uint32_t g_aatt[ROWS * 256];   // same layout (written by attn)
__device__ uint32_t g_bw1 [1536 * 256];   // [12 ntile][16 kc][2048 u32]
__device__ uint32_t g_bw2 [512 * 256];    // [4 ntile][...]
__device__ float    g_bias[1536];

// ------------------------------ helpers -----------------------------------
__device__ __forceinline__ uint32_t s2u32(const void* p) {
    uint32_t a;
    asm("{ .reg .u64 t; cvta.to.shared.u64 t, %1; cvt.u32.u64 %0, t; }"
        : "=r"(a) : "l"(p));
    return a;
}
__device__ __forceinline__ void cp16(uint32_t s, const void* g) {
    asm volatile("cp.async.cg.shared.global [%0], [%1], 16;" :: "r"(s), "l"(g));
}
#define CP_COMMIT() asm volatile("cp.async.commit_group;" ::: "memory")
#define CP_WAIT(n)  asm volatile("cp.async.wait_group %0;" :: "n"(n) : "memory")

__device__ __forceinline__ void lds128(uint32_t* r, uint32_t a) {
    asm volatile("ld.shared.v4.b32 {%0,%1,%2,%3}, [%4];"
                 : "=r"(r[0]), "=r"(r[1]), "=r"(r[2]), "=r"(r[3]) : "r"(a));
}
__device__ __forceinline__ void lds64(uint32_t* r, uint32_t a) {
    asm volatile("ld.shared.v2.b32 {%0,%1}, [%2];"
                 : "=r"(r[0]), "=r"(r[1]) : "r"(a));
}
__device__ __forceinline__ void mma_fp16(float* c, const uint32_t* a, const uint32_t* b) {
    asm volatile(
        "mma.sync.aligned.m16n8k16.row.col.f32.f16.f16.f32 "
        "{%0,%1,%2,%3}, {%4,%5,%6,%7}, {%8,%9}, {%0,%1,%2,%3};"
        : "+f"(c[0]), "+f"(c[1]), "+f"(c[2]), "+f"(c[3])
        : "r"(a[0]), "r"(a[1]), "r"(a[2]), "r"(a[3]), "r"(b[0]), "r"(b[1]));
}

// ------------------------------ pack (all) ---------------------------------
// blocks [0,1440): pack x -> g_ax ; [1440,1632): W_qkv -> g_bw1 (+bias)
// [1632,1696): Wp -> g_bw2
__global__ __launch_bounds__(256)
void pack_all(const float* __restrict__ x,
              const float* __restrict__ Wq, const float* __restrict__ Wk,
              const float* __restrict__ Wv, const float* __restrict__ Wp,
              const float* __restrict__ bq, const float* __restrict__ bk,
              const float* __restrict__ bv)
{
    const int b = blockIdx.x, t = threadIdx.x;
    if (b < 1440) {
        const int mtile = b >> 4, kc = b & 15;
        uint32_t* chunk = g_ax + ((size_t)mtile * 16 + kc) * 2048;
        const float* sbase = x + (size_t)mtile * 128 * 512 + kc * 32;
#pragma unroll
        for (int s = 0; s < 8; s++) {
            int p = t + s * 256;
            int blk = p >> 7, q = p & 127;
            int lane = q >> 2, reg = q & 3;
            int mb = blk >> 1, kb = blk & 1;
            int row = mb * 16 + (lane >> 2) + 8 * (reg & 1);
            int col = kb * 16 + (lane & 3) * 2 + 8 * (reg >> 1);
            float2 v = *(const float2*)(sbase + (size_t)row * 512 + col);
            __half2 h = __floats2half2_rn(v.x, v.y);
            chunk[p] = *(uint32_t*)&h;
        }
        return;
    }
    const int wb = b - 1440;
    const int is_p = wb >= 192;
    const int lb = is_p ? wb - 192 : wb;
    if (!is_p && wb < 6) {
        int i = wb * 256 + t;
        g_bias[i] = (i < 512) ? bq[i] : (i < 1024 ? bk[i - 512] : bv[i - 1024]);
    }
    uint32_t* dst = is_p ? g_bw2 : g_bw1;
    const int ntile = lb >> 4, kc = lb & 15;
    uint32_t* chunk = dst + ((size_t)ntile * 16 + kc) * 2048;
#pragma unroll
    for (int s = 0; s < 8; s++) {
        int p = t + s * 256;
        int blk = p >> 6, q = p & 63;
        int lane = q >> 1, reg = q & 1;
        int nb = blk >> 1, kb = blk & 1;
        int n = ntile * 128 + nb * 8 + (lane >> 2);
        int col = kc * 32 + kb * 16 + (lane & 3) * 2 + 8 * reg;
        const float* W = is_p ? Wp : ((n < 512) ? Wq : (n < 1024 ? Wk : Wv));
        float2 v = *(const float2*)(W + (size_t)(n & 511) * 512 + col);
        __half2 h = __floats2half2_rn(v.x, v.y);
        chunk[p] = *(uint32_t*)&h;
    }
}

// --------------------- GEMM QKV: 128x128 (R7 config) -----------------------
#define GSMEM (3 * 32768)

__global__ __launch_bounds__(256, 2)
void gemm_qkv(void)
{
    extern __shared__ __align__(16) char smem[];
    const uint32_t sb = s2u32(smem);
    const int t = threadIdx.x;
    const int wid = t >> 5, lane = t & 31;
    const int wm = wid & 1, wn = wid >> 1;

    const uint4* Ag = (const uint4*)g_ax + (size_t)blockIdx.x * 8192;
    const uint4* Bg = (const uint4*)g_bw1 + (size_t)blockIdx.y * 8192;

#define LOADS(c, stage) do {                                            \
        uint32_t s_ = sb + (stage) * 32768;                             \
        const uint4* ga_ = Ag + (c) * 1024 + t;                         \
        const uint4* gb_ = Bg + (c) * 1024 + t;                         \
        _Pragma("unroll")                                               \
        for (int i_ = 0; i_ < 4; i_++)                                  \
            cp16(s_ + (t + i_ * 256) * 16, ga_ + i_ * 256);             \
        _Pragma("unroll")                                               \
        for (int i_ = 0; i_ < 4; i_++)                                  \
            cp16(s_ + 16384 + (t + i_ * 256) * 16, gb_ + i_ * 256);     \
        CP_COMMIT();                                                    \
    } while (0)

    float acc[4][4][4];
#pragma unroll
    for (int i = 0; i < 4; i++)
#pragma unroll
        for (int j = 0; j < 4; j++)
#pragma unroll
            for (int r = 0; r < 4; r++) acc[i][j][r] = 0.f;

    LOADS(0, 0);
    LOADS(1, 1);

    uint32_t ah[2][4][4], bh[2][4][2];

    for (int c = 0; c < 8; c++) {
        if (c < 6) CP_WAIT(1);
        else       CP_WAIT(0);
        __syncthreads();

        if (c + 2 < 8) LOADS(c + 2, (c + 2) % 3);

        const uint32_t sa = sb + (c % 3) * 32768;
        const uint32_t sbm = sa + 16384;

#define AADDR(kb, i) (sa + (uint32_t)(((kb) >> 1) * 8192 + \
                       (((wm * 4 + (i)) * 2 + ((kb) & 1)) * 512 + lane * 16)))
#define BADDR(kb, j) (sbm + (uint32_t)(((kb) >> 1) * 8192 + \
                       (((wn * 4 + (j)) * 2 + ((kb) & 1)) * 256 + lane * 8)))

#pragma unroll
        for (int i = 0; i < 4; i++) lds128(ah[0][i], AADDR(0, i));
#pragma unroll
        for (int j = 0; j < 4; j++) lds64(bh[0][j], BADDR(0, j));

#pragma unroll
        for (int kb = 0; kb < 4; kb++) {
            const int cur = kb & 1, nxt = cur ^ 1;
            if (kb < 3) {
#pragma unroll
                for (int i = 0; i < 4; i++) lds128(ah[nxt][i], AADDR(kb + 1, i));
#pragma unroll
                for (int j = 0; j < 4; j++) lds64(bh[nxt][j], BADDR(kb + 1, j));
            }
#pragma unroll
            for (int i = 0; i < 4; i++)
#pragma unroll
                for (int j = 0; j < 4; j++)
                    mma_fp16(acc[i][j], ah[cur][i], bh[cur][j]);
        }
#undef AADDR
#undef BADDR
    }

    const int row0 = blockIdx.x * 128 + wm * 64 + (lane >> 2);
    const int colb = blockIdx.y * 128 + wn * 32 + (lane & 3) * 2;
#pragma unroll
    for (int i = 0; i < 4; i++)
#pragma unroll
        for (int j = 0; j < 4; j++) {
            const int r = row0 + i * 16;
            const int c = colb + j * 8;
            const float b0 = __ldg(g_bias + c), b1 = __ldg(g_bias + c + 1);
            *(float2*)(g_qkv + (size_t)r * 1536 + c) =
                make_float2(acc[i][j][0] + b0, acc[i][j][1] + b1);
            *(float2*)(g_qkv + (size_t)(r + 8) * 1536 + c) =
                make_float2(acc[i][j][2] + b0, acc[i][j][3] + b1);
        }
#undef LOADS
}

// --------------------- GEMM out-proj: 64x128 tiles -------------------------
// stage 24KB = [A 8K | B 16K], 3 stages. grid (180, 4).
#define GOSMEM (3 * 24576)

__global__ __launch_bounds__(256, 2)
void gemm_o(const float* __restrict__ bias, float* __restrict__ C)
{
    extern __shared__ __align__(16) char smem[];
    const uint32_t sb = s2u32(smem);
    const int t = threadIdx.x;
    const int wid = t >> 5, lane = t & 31;
    const int wm = wid & 1, wn = wid >> 1;

    const int mtile = blockIdx.x >> 1, mh = blockIdx.x & 1;
    const uint4* Ag = (const uint4*)g_aatt + (size_t)mtile * 8192;
    const uint4* Bg = (const uint4*)g_bw2 + (size_t)blockIdx.y * 8192;

    // macro-chunk c = kc pair {2c,2c+1}; A rows [mh*64, mh*64+64)
#define LOADO(c, stage) do {                                            \
        uint32_t s_ = sb + (stage) * 24576;                             \
        const uint4* ga0_ = Ag + (c) * 1024 + mh * 256 + t;             \
        const uint4* ga1_ = Ag + (c) * 1024 + 512 + mh * 256 + t;       \
        cp16(s_ + t * 16, ga0_);                                        \
        cp16(s_ + 4096 + t * 16, ga1_);                                 \
        const uint4* gb_ = Bg + (c) * 1024 + t;                         \
        _Pragma("unroll")                                               \
        for (int i_ = 0; i_ < 4; i_++)                                  \
            cp16(s_ + 8192 + (t + i_ * 256) * 16, gb_ + i_ * 256);      \
        CP_COMMIT();                                                    \
    } while (0)

    float acc[2][4][4];
#pragma unroll
    for (int i = 0; i < 2; i++)
#pragma unroll
        for (int j = 0; j < 4; j++)
#pragma unroll
            for (int r = 0; r < 4; r++) acc[i][j][r] = 0.f;

    LOADO(0, 0);
    LOADO(1, 1);

    uint32_t ah[2][2][4], bh[2][4][2];

    for (int c = 0; c < 8; c++) {
        if (c < 6) CP_WAIT(1);
        else       CP_WAIT(0);
        __syncthreads();

        if (c + 2 < 8) LOADO(c + 2, (c + 2) % 3);

        const uint32_t sa = sb + (c % 3) * 24576;
        const uint32_t sbm = sa + 8192;

#define AADDR(kb, i) (sa + (uint32_t)(((kb) >> 1) * 4096 + \
                       (((wm * 2 + (i)) * 2 + ((kb) & 1)) * 512 + lane * 16)))
#define BADDR(kb, j) (sbm + (uint32_t)(((kb) >> 1) * 8192 + \
                       (((wn * 4 + (j)) * 2 + ((kb) & 1)) * 256 + lane * 8)))

#pragma unroll
        for (int i = 0; i < 2; i++) lds128(ah[0][i], AADDR(0, i));
#pragma unroll
        for (int j = 0; j < 4; j++) lds64(bh[0][j], BADDR(0, j));

#pragma unroll
        for (int kb = 0; kb < 4; kb++) {
            const int cur = kb & 1, nxt = cur ^ 1;
            if (kb < 3) {
#pragma unroll
                for (int i = 0; i < 2; i++) lds128(ah[nxt][i], AADDR(kb + 1, i));
#pragma unroll
                for (int j = 0; j < 4; j++) lds64(bh[nxt][j], BADDR(kb + 1, j));
            }
#pragma unroll
            for (int i = 0; i < 2; i++)
#pragma unroll
                for (int j = 0; j < 4; j++)
                    mma_fp16(acc[i][j], ah[cur][i], bh[cur][j]);
        }
#undef AADDR
#undef BADDR
    }

    const int row0 = blockIdx.x * 64 + wm * 32 + (lane >> 2);
    const int colb = blockIdx.y * 128 + wn * 32 + (lane & 3) * 2;
#pragma unroll
    for (int i = 0; i < 2; i++)
#pragma unroll
        for (int j = 0; j < 4; j++) {
            const int r = row0 + i * 16;
            const int c = colb + j * 8;
            const float b0 = __ldg(bias + c), b1 = __ldg(bias + c + 1);
            *(float2*)(C + (size_t)r * 512 + c) =
                make_float2(acc[i][j][0] + b0, acc[i][j][1] + b1);
            *(float2*)(C + (size_t)(r + 8) * 512 + c) =
                make_float2(acc[i][j][2] + b0, acc[i][j][3] + b1);
        }
#undef LOADO
}

// ----------------------------- attention -----------------------------------
// block=(bm, head). 8-lane groups: each group owns one query; dot over D=64 as
// 8 regs/lane + 3-shfl reduce. Output pairs live in-lane -> shfl-free pack.
__global__ __launch_bounds__(256)
void attn_kernel(const int* __restrict__ pair_idxs)
{
    __shared__ float ks[45 * 64];
    __shared__ float vs[45 * 64];
    __shared__ int sp[45 * 17];

    const int bm = blockIdx.x;   // 0..255
    const int n = blockIdx.y;    // 0..7
    const int base = bm * 45;
    const int tid = threadIdx.x;

    for (int i = tid; i < 45 * 17; i += 256) sp[i] = pair_idxs[i];
    for (int i = tid; i < 45 * 16; i += 256) {
        const int r = i >> 4, c4 = (i & 15) * 4;
        const float* src = g_qkv + (size_t)(base + r) * 1536 + n * 64 + c4;
        *(float4*)&ks[r * 64 + c4] = *(const float4*)(src + 512);
        *(float4*)&vs[r * 64 + c4] = *(const float4*)(src + 1024);
    }
    __syncthreads();

    const int warp = tid >> 5, lane = tid & 31;
    const int g = lane >> 3, li = lane & 7;

#pragma unroll
    for (int it = 0; it < 2; it++) {
        const int qidx = it * 32 + warp * 4 + g;
        const bool active = qidx < 45;
        const int qc = active ? qidx : 0;

        float q[8];
        {
            const float* qrow = g_qkv + (size_t)(base + qc) * 1536 + n * 64 + li * 8;
            float4 a = *(const float4*)qrow;
            float4 b = *(const float4*)(qrow + 4);
            q[0] = a.x; q[1] = a.y; q[2] = a.z; q[3] = a.w;
            q[4] = b.x; q[5] = b.y; q[6] = b.z; q[7] = b.w;
        }

        float sc[17];
        int tj[17];
#pragma unroll
        for (int j = 0; j < 17; j++) {
            tj[j] = sp[qc * 17 + j];
            const float* kr = ks + tj[j] * 64 + li * 8;
            float4 a = *(const float4*)kr;
            float4 b = *(const float4*)(kr + 4);
            float p = q[0] * a.x + q[1] * a.y + q[2] * a.z + q[3] * a.w
                    + q[4] * b.x + q[5] * b.y + q[6] * b.z + q[7] * b.w;
            p += __shfl_xor_sync(0xffffffffu, p, 4);
            p += __shfl_xor_sync(0xffffffffu, p, 2);
            p += __shfl_xor_sync(0xffffffffu, p, 1);
            sc[j] = p * 0.125f;
        }
        float mx = sc[0];
#pragma unroll
        for (int j = 1; j < 17; j++) mx = fmaxf(mx, sc[j]);
        float ssum = 0.f;
#pragma unroll
        for (int j = 0; j < 17; j++) { sc[j] = __expf(sc[j] - mx); ssum += sc[j]; }
        const float inv = 1.f / ssum;

        float o[8];
#pragma unroll
        for (int i = 0; i < 8; i++) o[i] = 0.f;
#pragma unroll
        for (int j = 0; j < 17; j++) {
            const float* vr = vs + tj[j] * 64 + li * 8;
            float4 a = *(const float4*)vr;
            float4 b = *(const float4*)(vr + 4);
            const float w = sc[j] * inv;
            o[0] += w * a.x; o[1] += w * a.y; o[2] += w * a.z; o[3] += w * a.w;
            o[4] += w * b.x; o[5] += w * b.y; o[6] += w * b.z; o[7] += w * b.w;
        }

        if (active) {
            // fragment pack (shfl-free): lane li covers cols [li*8, li*8+8)
            const int grow = base + qidx;
            const int mtile = grow >> 7;
            const int rr = grow & 127;
            const int rbit = (rr >> 3) & 1;
            const int mb = rr >> 4;
            const int kc = n * 2 + (li >> 2);
            const int kb = (li >> 1) & 1;
            const int reg = rbit + 2 * (li & 1);
            uint32_t* cbase = g_aatt + ((size_t)mtile * 16 + kc) * 2048
                              + (mb * 2 + kb) * 128 + reg;
#pragma unroll
            for (int c = 0; c < 4; c++) {
                __half2 h = __floats2half2_rn(o[2 * c], o[2 * c + 1]);
                cbase[((rr & 7) * 4 + c) * 4] = *(uint32_t*)&h;
            }
        }
    }
}

// ------------------------------- launch ------------------------------------
extern "C" void kernel_launch(void* const* d_in, const int* in_sizes, int n_in,
                              void* d_out, int out_size)
{
    const float* x  = (const float*)d_in[0];
    const float* Wq = (const float*)d_in[1];
    const float* bq = (const float*)d_in[2];
    const float* Wk = (const float*)d_in[3];
    const float* bk = (const float*)d_in[4];
    const float* Wv = (const float*)d_in[5];
    const float* bv = (const float*)d_in[6];
    const float* Wp = (const float*)d_in[7];
    const float* bp = (const float*)d_in[8];
    const int* pair = (const int*)d_in[9];
    float* out = (float*)d_out;
    (void)in_sizes; (void)n_in; (void)out_size;

    cudaFuncSetAttribute(gemm_qkv, cudaFuncAttributeMaxDynamicSharedMemorySize, GSMEM);
    cudaFuncSetAttribute(gemm_o, cudaFuncAttributeMaxDynamicSharedMemorySize, GOSMEM);

    pack_all<<<1696, 256>>>(x, Wq, Wk, Wv, Wp, bq, bk, bv);
    gemm_qkv<<<dim3(90, 12), 256, GSMEM>>>();
    attn_kernel<<<dim3(256, 8), 256>>>(pair);
    gemm_o<<<dim3(180, 4), 256, GOSMEM>>>(bp, out);
}